// round 2
// baseline (speedup 1.0000x reference)
#include <cuda_runtime.h>
#include <math.h>

#define HH 80
#define WW 80
#define CI 256
#define NF 128
#define NPIX (HH*WW)   // 6400
#define BATCH 2

// Scratch (device globals; no allocations allowed)
__device__ float g_qkv[3][BATCH][NPIX*NF];   // theta, phi(flat), g
__device__ float g_att[BATCH][NPIX*NF];      // attention output (n, c)

// ---------------------------------------------------------------------------
// Conv 3x3 SAME, CIN=256 -> CO=128, computes theta/phi/g (blockIdx.z % 3)
// Block: 256 threads, tile = 16 pixels (one row segment) x 128 out channels.
// Thread t: co = t%128, pixel group (t/128)*8 .. +7.
// ---------------------------------------------------------------------------
__global__ __launch_bounds__(256) void conv_qkv_kernel(
    const float* __restrict__ x,
    const float* __restrict__ w0,
    const float* __restrict__ w1,
    const float* __restrict__ w2)
{
    extern __shared__ float s_in[];            // [3][CI][21] (18 used, pad 21)
    const int xt = blockIdx.x;                 // 0..4
    const int y  = blockIdx.y;                 // 0..79
    const int b  = blockIdx.z / 3;
    const int cv = blockIdx.z % 3;
    const float* __restrict__ wgt = (cv == 0) ? w0 : ((cv == 1) ? w1 : w2);
    float* __restrict__ outp = g_qkv[cv][b];
    const int x0 = xt * 16;
    const int t  = threadIdx.x;

    // Cooperative patch load: rows y-1..y+1, x0-1..x0+16, all 256 ci (coalesced on ci)
    for (int i = t; i < 3 * 18 * CI; i += 256) {
        int ci = i & (CI - 1);
        int xi = (i >> 8) % 18;
        int r  = i / (18 * CI);
        int gy = y - 1 + r, gx = x0 - 1 + xi;
        float v = 0.f;
        if (gy >= 0 && gy < HH && gx >= 0 && gx < WW)
            v = x[((b * HH + gy) * WW + gx) * CI + ci];
        s_in[(r * CI + ci) * 21 + xi] = v;
    }
    __syncthreads();

    const int co  = t & (NF - 1);
    const int pxb = (t >> 7) * 8;

    float acc[8];
#pragma unroll
    for (int p = 0; p < 8; p++) acc[p] = 0.f;

    for (int ky = 0; ky < 3; ky++) {
#pragma unroll 4
        for (int ci = 0; ci < CI; ci++) {
            const float* row = &s_in[(ky * CI + ci) * 21 + pxb];
            float win[10];
#pragma unroll
            for (int i = 0; i < 10; i++) win[i] = row[i];   // LDS broadcast within warp
#pragma unroll
            for (int kx = 0; kx < 3; kx++) {
                float wv = wgt[((ky * 3 + kx) * CI + ci) * NF + co]; // coalesced over co
#pragma unroll
                for (int p = 0; p < 8; p++)
                    acc[p] = fmaf(win[p + kx], wv, acc[p]);
            }
        }
    }
    const int nbase = y * WW + x0 + pxb;
#pragma unroll
    for (int p = 0; p < 8; p++)
        outp[(nbase + p) * NF + co] = acc[p];
}

// ---------------------------------------------------------------------------
// Flash attention: out = softmax(theta @ phiview) @ g,  N=6400, d=128.
// phiview(c, m) = phi_flat[c*6400 + m]  (the Keras row-major reshape).
// Grid: (50 q-tiles, 2 batches). Block 256 threads. Tiles 128x128x128.
// smem: Qst[c][i] (Q transposed) + Bs (K-chunk, reused as P) + Gs. Pad 132.
// ---------------------------------------------------------------------------
#define LD 132
#define SM_Q 0
#define SM_B (128*LD)
#define SM_G (2*128*LD)

__global__ __launch_bounds__(256, 1) void flash_kernel()
{
    extern __shared__ float sm[];
    float* Qst = sm + SM_Q;
    float* Bs  = sm + SM_B;   // K-chunk, then reused as P
    float* Gs  = sm + SM_G;

    const int b  = blockIdx.y;
    const int q0 = blockIdx.x * 128;
    const float* __restrict__ theta = g_qkv[0][b];
    const float* __restrict__ phi   = g_qkv[1][b];
    const float* __restrict__ gmat  = g_qkv[2][b];

    const int t  = threadIdx.x;
    const int tx = t & 15, ty = t >> 4;
    const int i0 = ty * 8, j0 = tx * 8;

    // Load Q tile transposed: Qst[c*LD + i]
    for (int idx = t; idx < 128 * 128; idx += 256) {
        int i = idx >> 7, c = idx & 127;
        Qst[c * LD + i] = theta[(q0 + i) * NF + c];
    }

    float o[8][8];
    float mrun[8], lrun[8];
#pragma unroll
    for (int ii = 0; ii < 8; ii++) {
        mrun[ii] = -1e30f; lrun[ii] = 0.f;
#pragma unroll
        for (int cc = 0; cc < 8; cc++) o[ii][cc] = 0.f;
    }
    __syncthreads();

    for (int km = 0; km < 50; km++) {
        const int m0 = km * 128;
        // Load K-chunk (phiview rows) and G-chunk
        for (int idx = t; idx < 128 * 128; idx += 256) {
            int r = idx >> 7, c2 = idx & 127;
            Bs[r * LD + c2] = phi[r * NPIX + m0 + c2];      // B(c=r, m0+c2)
            Gs[r * LD + c2] = gmat[(m0 + r) * NF + c2];     // G(j=r, ch=c2)
        }
        __syncthreads();

        // GEMM1: S = Q @ B  (128x128x128)
        float s[8][8];
#pragma unroll
        for (int ii = 0; ii < 8; ii++)
#pragma unroll
            for (int jj = 0; jj < 8; jj++) s[ii][jj] = 0.f;

        for (int c = 0; c < 128; c++) {
            float4 a0 = *(const float4*)&Qst[c * LD + i0];
            float4 a1 = *(const float4*)&Qst[c * LD + i0 + 4];
            float4 b0 = *(const float4*)&Bs[c * LD + j0];
            float4 b1 = *(const float4*)&Bs[c * LD + j0 + 4];
            float av[8] = {a0.x, a0.y, a0.z, a0.w, a1.x, a1.y, a1.z, a1.w};
            float bv[8] = {b0.x, b0.y, b0.z, b0.w, b1.x, b1.y, b1.z, b1.w};
#pragma unroll
            for (int ii = 0; ii < 8; ii++)
#pragma unroll
                for (int jj = 0; jj < 8; jj++)
                    s[ii][jj] = fmaf(av[ii], bv[jj], s[ii][jj]);
        }
        __syncthreads();   // done reading Bs; safe to overwrite with P

        // Online softmax update (row stats reduced across the 16 tx lanes)
#pragma unroll
        for (int ii = 0; ii < 8; ii++) {
            float mx = s[ii][0];
#pragma unroll
            for (int jj = 1; jj < 8; jj++) mx = fmaxf(mx, s[ii][jj]);
            mx = fmaxf(mx, __shfl_xor_sync(0xffffffffu, mx, 1));
            mx = fmaxf(mx, __shfl_xor_sync(0xffffffffu, mx, 2));
            mx = fmaxf(mx, __shfl_xor_sync(0xffffffffu, mx, 4));
            mx = fmaxf(mx, __shfl_xor_sync(0xffffffffu, mx, 8));
            float mnew = fmaxf(mrun[ii], mx);
            float f = __expf(mrun[ii] - mnew);
            mrun[ii] = mnew;
            float sum = 0.f;
#pragma unroll
            for (int jj = 0; jj < 8; jj++) {
                float p = __expf(s[ii][jj] - mnew);
                s[ii][jj] = p;
                sum += p;
            }
            sum += __shfl_xor_sync(0xffffffffu, sum, 1);
            sum += __shfl_xor_sync(0xffffffffu, sum, 2);
            sum += __shfl_xor_sync(0xffffffffu, sum, 4);
            sum += __shfl_xor_sync(0xffffffffu, sum, 8);
            lrun[ii] = lrun[ii] * f + sum;
#pragma unroll
            for (int cc = 0; cc < 8; cc++) o[ii][cc] *= f;
        }

        // Store P into Bs region: Ps[i][j]
#pragma unroll
        for (int ii = 0; ii < 8; ii++) {
            *(float4*)&Bs[(i0 + ii) * LD + j0]     = make_float4(s[ii][0], s[ii][1], s[ii][2], s[ii][3]);
            *(float4*)&Bs[(i0 + ii) * LD + j0 + 4] = make_float4(s[ii][4], s[ii][5], s[ii][6], s[ii][7]);
        }
        __syncthreads();

        // GEMM2: O += P @ G   (channels = j0..j0+7 for this thread)
        for (int j = 0; j < 128; j++) {
            float4 g0 = *(const float4*)&Gs[j * LD + j0];
            float4 g1 = *(const float4*)&Gs[j * LD + j0 + 4];
            float gv[8] = {g0.x, g0.y, g0.z, g0.w, g1.x, g1.y, g1.z, g1.w};
#pragma unroll
            for (int ii = 0; ii < 8; ii++) {
                float pv = Bs[(i0 + ii) * LD + j];   // broadcast LDS
#pragma unroll
                for (int cc = 0; cc < 8; cc++)
                    o[ii][cc] = fmaf(pv, gv[cc], o[ii][cc]);
            }
        }
        __syncthreads();   // GEMM2 reads done before next chunk's loads
    }

    // Epilogue: normalize and store (n, c) layout
#pragma unroll
    for (int ii = 0; ii < 8; ii++) {
        float inv = 1.f / lrun[ii];
        float* dst = &g_att[b][(q0 + i0 + ii) * NF + j0];
        *(float4*)&dst[0] = make_float4(o[ii][0] * inv, o[ii][1] * inv, o[ii][2] * inv, o[ii][3] * inv);
        *(float4*)&dst[4] = make_float4(o[ii][4] * inv, o[ii][5] * inv, o[ii][6] * inv, o[ii][7] * inv);
    }
}

// ---------------------------------------------------------------------------
// Final conv 3x3, 128 -> 256, + residual add, writes d_out.
// Block: 256 threads, tile = 16 pixels x 256 co; thread t owns co = t, 16 px.
// ---------------------------------------------------------------------------
__global__ __launch_bounds__(256) void conv_final_kernel(
    const float* __restrict__ x,
    const float* __restrict__ wc,
    float* __restrict__ out)
{
    extern __shared__ float s_in[];            // [3][128][21]
    const int xt = blockIdx.x;                 // 0..4
    const int y  = blockIdx.y;
    const int b  = blockIdx.z;
    const int x0 = xt * 16;
    const int t  = threadIdx.x;                // co = t
    const float* __restrict__ ain = g_att[b];

    for (int i = t; i < 3 * 18 * NF; i += 256) {
        int ci = i & (NF - 1);
        int xi = (i >> 7) % 18;
        int r  = i / (18 * NF);
        int gy = y - 1 + r, gx = x0 - 1 + xi;
        float v = 0.f;
        if (gy >= 0 && gy < HH && gx >= 0 && gx < WW)
            v = ain[(gy * WW + gx) * NF + ci];
        s_in[(r * NF + ci) * 21 + xi] = v;
    }
    __syncthreads();

    float acc[16];
#pragma unroll
    for (int p = 0; p < 16; p++) acc[p] = 0.f;

    for (int ky = 0; ky < 3; ky++) {
#pragma unroll 2
        for (int ci = 0; ci < NF; ci++) {
            const float* row = &s_in[(ky * NF + ci) * 21];
            float win[18];
#pragma unroll
            for (int i = 0; i < 18; i++) win[i] = row[i];
#pragma unroll
            for (int kx = 0; kx < 3; kx++) {
                float wv = wc[((ky * 3 + kx) * NF + ci) * CI + t];
#pragma unroll
                for (int p = 0; p < 16; p++)
                    acc[p] = fmaf(win[p + kx], wv, acc[p]);
            }
        }
    }
#pragma unroll
    for (int p = 0; p < 16; p++) {
        int gi = ((b * HH + y) * WW + x0 + p) * CI + t;
        out[gi] = x[gi] + acc[p];
    }
}

// ---------------------------------------------------------------------------
extern "C" void kernel_launch(void* const* d_in, const int* in_sizes, int n_in,
                              void* d_out, int out_size)
{
    const float* x  = (const float*)d_in[0];
    const float* wt = (const float*)d_in[1];
    const float* wp = (const float*)d_in[2];
    const float* wg = (const float*)d_in[3];
    const float* wc = (const float*)d_in[4];
    float* out = (float*)d_out;

    const int smem_qkv   = 3 * CI * 21 * 4;        // 64512
    const int smem_flash = 3 * 128 * LD * 4;       // 202752
    const int smem_final = 3 * NF * 21 * 4;        // 32256

    cudaFuncSetAttribute(conv_qkv_kernel,  cudaFuncAttributeMaxDynamicSharedMemorySize, smem_qkv);
    cudaFuncSetAttribute(flash_kernel,     cudaFuncAttributeMaxDynamicSharedMemorySize, smem_flash);
    cudaFuncSetAttribute(conv_final_kernel, cudaFuncAttributeMaxDynamicSharedMemorySize, smem_final);

    conv_qkv_kernel<<<dim3(5, 80, 6), 256, smem_qkv>>>(x, wt, wp, wg);
    flash_kernel<<<dim3(50, 2), 256, smem_flash>>>();
    conv_final_kernel<<<dim3(5, 80, 2), 256, smem_final>>>(x, wc, out);
}

// round 3
// speedup vs baseline: 1.2458x; 1.2458x over previous
#include <cuda_runtime.h>
#include <math.h>

#define HH 80
#define WW 80
#define CI 256
#define NF 128
#define NPIX (HH*WW)   // 6400
#define BATCH 2

// Scratch (device globals; no allocations allowed)
__device__ float g_qkv[3][BATCH][NPIX*NF];   // theta, phi(flat), g
__device__ float g_att[BATCH][NPIX*NF];      // attention output (n, c)

// ---------------- packed f32x2 helpers (FFMA2 via PTX) ----------------------
typedef unsigned long long ull;

__device__ __forceinline__ ull pack2(float lo, float hi) {
    ull r; asm("mov.b64 %0, {%1, %2};" : "=l"(r) : "f"(lo), "f"(hi)); return r;
}
__device__ __forceinline__ ull dup2(float v) { return pack2(v, v); }
__device__ __forceinline__ void fma2(ull& d, ull a, ull b) {
    asm("fma.rn.f32x2 %0, %1, %2, %3;" : "=l"(d) : "l"(a), "l"(b), "l"(d));
}
__device__ __forceinline__ float2 unpk(ull v) {
    float2 f; asm("mov.b64 {%0, %1}, %2;" : "=f"(f.x), "=f"(f.y) : "l"(v)); return f;
}

// ---------------------------------------------------------------------------
// Conv 3x3 SAME, CIN=256 -> CO=128, computes theta/phi/g (blockIdx.z % 3)
// Block: 256 threads. Thread t: co = t%128, 8 pixels (t/128)*8..+7.
// smem rows padded to 20 floats -> vectorized (aligned) window loads.
// ---------------------------------------------------------------------------
#define PADQ 20
__global__ __launch_bounds__(256) void conv_qkv_kernel(
    const float* __restrict__ x,
    const float* __restrict__ w0,
    const float* __restrict__ w1,
    const float* __restrict__ w2)
{
    extern __shared__ float s_in[];            // [3][CI][PADQ] (18 used)
    const int xt = blockIdx.x;                 // 0..4
    const int y  = blockIdx.y;                 // 0..79
    const int b  = blockIdx.z / 3;
    const int cv = blockIdx.z % 3;
    const float* __restrict__ wgt = (cv == 0) ? w0 : ((cv == 1) ? w1 : w2);
    float* __restrict__ outp = g_qkv[cv][b];
    const int x0 = xt * 16;
    const int t  = threadIdx.x;

    for (int i = t; i < 3 * 18 * CI; i += 256) {
        int ci = i & (CI - 1);
        int xi = (i >> 8) % 18;
        int r  = i / (18 * CI);
        int gy = y - 1 + r, gx = x0 - 1 + xi;
        float v = 0.f;
        if (gy >= 0 && gy < HH && gx >= 0 && gx < WW)
            v = x[((b * HH + gy) * WW + gx) * CI + ci];
        s_in[(r * CI + ci) * PADQ + xi] = v;
    }
    __syncthreads();

    const int co  = t & (NF - 1);
    const int pxb = (t >> 7) * 8;

    ull acc[4];
#pragma unroll
    for (int p = 0; p < 4; p++) acc[p] = dup2(0.f);

    for (int ky = 0; ky < 3; ky++) {
#pragma unroll 4
        for (int ci = 0; ci < CI; ci++) {
            const float* row = &s_in[(ky * CI + ci) * PADQ + pxb];
            float4 wA = *(const float4*)&row[0];
            float4 wB = *(const float4*)&row[4];
            float2 wC = *(const float2*)&row[8];
            // even pairs (aligned; ptxas should elide the packs)
            ull p0 = pack2(wA.x, wA.y), p1 = pack2(wA.z, wA.w);
            ull p2 = pack2(wB.x, wB.y), p3 = pack2(wB.z, wB.w);
            ull p4 = pack2(wC.x, wC.y);
            // odd pairs (kx = 1)
            ull q0 = pack2(wA.y, wA.z), q1 = pack2(wA.w, wB.x);
            ull q2 = pack2(wB.y, wB.z), q3 = pack2(wB.w, wC.x);

            const float* wb = &wgt[((ky * 3) * CI + ci) * NF + co];
            ull wv0 = dup2(wb[0]);
            ull wv1 = dup2(wb[CI * NF]);
            ull wv2 = dup2(wb[2 * CI * NF]);

            fma2(acc[0], p0, wv0); fma2(acc[1], p1, wv0);
            fma2(acc[2], p2, wv0); fma2(acc[3], p3, wv0);
            fma2(acc[0], q0, wv1); fma2(acc[1], q1, wv1);
            fma2(acc[2], q2, wv1); fma2(acc[3], q3, wv1);
            fma2(acc[0], p1, wv2); fma2(acc[1], p2, wv2);
            fma2(acc[2], p3, wv2); fma2(acc[3], p4, wv2);
        }
    }
    const int nbase = y * WW + x0 + pxb;
#pragma unroll
    for (int p = 0; p < 4; p++) {
        float2 v = unpk(acc[p]);
        outp[(nbase + 2 * p)     * NF + co] = v.x;
        outp[(nbase + 2 * p + 1) * NF + co] = v.y;
    }
}

// ---------------------------------------------------------------------------
// Flash attention: out = softmax(theta @ phiview) @ g,  N=6400, d=128.
// phiview(c, m) = phi_flat[c*6400 + m]. Q-tile = 96 rows -> 67x2=134 CTAs
// (one full wave on 148 SMs). Block 256 threads, frag 6x8, packed f32x2.
// ---------------------------------------------------------------------------
#define LD  132
#define LDQ 100
#define QROWS 96
#define SM_Q 0
#define SM_B (128*LDQ)
#define SM_G (128*LDQ + 128*LD)

__global__ __launch_bounds__(256, 1) void flash_kernel()
{
    extern __shared__ float sm[];
    float* Qst = sm + SM_Q;   // [c][i] transposed, i < 96
    float* Bs  = sm + SM_B;   // K-chunk, then reused as P
    float* Gs  = sm + SM_G;

    const int b  = blockIdx.y;
    const int q0 = blockIdx.x * QROWS;
    const float* __restrict__ theta = g_qkv[0][b];
    const float* __restrict__ phi   = g_qkv[1][b];
    const float* __restrict__ gmat  = g_qkv[2][b];

    const int t  = threadIdx.x;
    const int tx = t & 15, ty = t >> 4;
    const int i0 = ty * 6, j0 = tx * 8;

    // Load Q tile transposed: Qst[c*LDQ + i]  (rows clamped at edge tile)
    for (int idx = t; idx < QROWS * 128; idx += 256) {
        int i = idx >> 7, c = idx & 127;
        int qi = q0 + i; if (qi >= NPIX) qi = NPIX - 1;
        Qst[c * LDQ + i] = theta[qi * NF + c];
    }

    ull o2[6][4];
    float mrun[6], lrun[6];
#pragma unroll
    for (int ii = 0; ii < 6; ii++) {
        mrun[ii] = -1e30f; lrun[ii] = 0.f;
#pragma unroll
        for (int cp = 0; cp < 4; cp++) o2[ii][cp] = dup2(0.f);
    }
    __syncthreads();

    for (int km = 0; km < 50; km++) {
        const int m0 = km * 128;
        for (int idx = t; idx < 128 * 128; idx += 256) {
            int r = idx >> 7, c2 = idx & 127;
            Bs[r * LD + c2] = phi[r * NPIX + m0 + c2];      // B(c=r, m0+c2)
            Gs[r * LD + c2] = gmat[(m0 + r) * NF + c2];     // G(j=r, ch=c2)
        }
        __syncthreads();

        // GEMM1: S = Q @ B  (96x128x128), packed along j
        ull s2[6][4];
#pragma unroll
        for (int ii = 0; ii < 6; ii++)
#pragma unroll
            for (int jp = 0; jp < 4; jp++) s2[ii][jp] = dup2(0.f);

        for (int c = 0; c < 128; c++) {
            const float* qrow = &Qst[c * LDQ + i0];
            float2 a01 = *(const float2*)&qrow[0];
            float2 a23 = *(const float2*)&qrow[2];
            float2 a45 = *(const float2*)&qrow[4];
            ull av[6] = {dup2(a01.x), dup2(a01.y), dup2(a23.x),
                         dup2(a23.y), dup2(a45.x), dup2(a45.y)};
            const ulonglong2* brow = (const ulonglong2*)&Bs[c * LD + j0];
            ulonglong2 b01 = brow[0], b23 = brow[1];
            ull bv[4] = {b01.x, b01.y, b23.x, b23.y};
#pragma unroll
            for (int ii = 0; ii < 6; ii++)
#pragma unroll
                for (int jp = 0; jp < 4; jp++)
                    fma2(s2[ii][jp], av[ii], bv[jp]);
        }
        __syncthreads();   // done reading Bs; safe to overwrite with P

        // Online softmax update (row stats reduced across the 16 tx lanes)
#pragma unroll
        for (int ii = 0; ii < 6; ii++) {
            float sv[8];
            float2 u;
            u = unpk(s2[ii][0]); sv[0] = u.x; sv[1] = u.y;
            u = unpk(s2[ii][1]); sv[2] = u.x; sv[3] = u.y;
            u = unpk(s2[ii][2]); sv[4] = u.x; sv[5] = u.y;
            u = unpk(s2[ii][3]); sv[6] = u.x; sv[7] = u.y;
            float mx = sv[0];
#pragma unroll
            for (int jj = 1; jj < 8; jj++) mx = fmaxf(mx, sv[jj]);
            mx = fmaxf(mx, __shfl_xor_sync(0xffffffffu, mx, 1));
            mx = fmaxf(mx, __shfl_xor_sync(0xffffffffu, mx, 2));
            mx = fmaxf(mx, __shfl_xor_sync(0xffffffffu, mx, 4));
            mx = fmaxf(mx, __shfl_xor_sync(0xffffffffu, mx, 8));
            float mnew = fmaxf(mrun[ii], mx);
            float f = __expf(mrun[ii] - mnew);
            mrun[ii] = mnew;
            float sum = 0.f;
#pragma unroll
            for (int jj = 0; jj < 8; jj++) {
                float p = __expf(sv[jj] - mnew);
                sv[jj] = p;
                sum += p;
            }
            sum += __shfl_xor_sync(0xffffffffu, sum, 1);
            sum += __shfl_xor_sync(0xffffffffu, sum, 2);
            sum += __shfl_xor_sync(0xffffffffu, sum, 4);
            sum += __shfl_xor_sync(0xffffffffu, sum, 8);
            lrun[ii] = lrun[ii] * f + sum;
            ull f2v = dup2(f);
#pragma unroll
            for (int cp = 0; cp < 4; cp++) {
                ull z = dup2(0.f);
                fma2(z, o2[ii][cp], f2v);   // o *= f
                o2[ii][cp] = z;
            }
            // stash P row into Bs (P[i][j] layout)
            *(float4*)&Bs[(i0 + ii) * LD + j0]     = make_float4(sv[0], sv[1], sv[2], sv[3]);
            *(float4*)&Bs[(i0 + ii) * LD + j0 + 4] = make_float4(sv[4], sv[5], sv[6], sv[7]);
        }
        __syncthreads();

        // GEMM2: O += P @ G  (channels j0..j0+7, packed)
        for (int j = 0; j < 128; j++) {
            const ulonglong2* grow = (const ulonglong2*)&Gs[j * LD + j0];
            ulonglong2 g01 = grow[0], g23 = grow[1];
            ull gv[4] = {g01.x, g01.y, g23.x, g23.y};
#pragma unroll
            for (int ii = 0; ii < 6; ii++) {
                ull pv = dup2(Bs[(i0 + ii) * LD + j]);   // broadcast LDS
#pragma unroll
                for (int cp = 0; cp < 4; cp++)
                    fma2(o2[ii][cp], pv, gv[cp]);
            }
        }
        __syncthreads();   // GEMM2 reads done before next chunk's loads
    }

    // Epilogue: normalize and store (n, c) layout
#pragma unroll
    for (int ii = 0; ii < 6; ii++) {
        int row = q0 + i0 + ii;
        if (row >= NPIX) continue;
        float inv = 1.f / lrun[ii];
        float2 v0 = unpk(o2[ii][0]), v1 = unpk(o2[ii][1]);
        float2 v2 = unpk(o2[ii][2]), v3 = unpk(o2[ii][3]);
        float* dst = &g_att[b][row * NF + j0];
        *(float4*)&dst[0] = make_float4(v0.x * inv, v0.y * inv, v1.x * inv, v1.y * inv);
        *(float4*)&dst[4] = make_float4(v2.x * inv, v2.y * inv, v3.x * inv, v3.y * inv);
    }
}

// ---------------------------------------------------------------------------
// Final conv 3x3, 128 -> 256, + residual add, writes d_out.
// Block: 256 threads, thread t owns co = t, 16 pixels. Packed f32x2.
// ---------------------------------------------------------------------------
#define PADF 20
__global__ __launch_bounds__(256) void conv_final_kernel(
    const float* __restrict__ x,
    const float* __restrict__ wc,
    float* __restrict__ out)
{
    extern __shared__ float s_in[];            // [3][128][PADF]
    const int xt = blockIdx.x;                 // 0..4
    const int y  = blockIdx.y;
    const int b  = blockIdx.z;
    const int x0 = xt * 16;
    const int t  = threadIdx.x;                // co = t
    const float* __restrict__ ain = g_att[b];

    for (int i = t; i < 3 * 18 * NF; i += 256) {
        int ci = i & (NF - 1);
        int xi = (i >> 7) % 18;
        int r  = i / (18 * NF);
        int gy = y - 1 + r, gx = x0 - 1 + xi;
        float v = 0.f;
        if (gy >= 0 && gy < HH && gx >= 0 && gx < WW)
            v = ain[(gy * WW + gx) * NF + ci];
        s_in[(r * NF + ci) * PADF + xi] = v;
    }
    __syncthreads();

    ull acc[8];
#pragma unroll
    for (int p = 0; p < 8; p++) acc[p] = dup2(0.f);

    for (int ky = 0; ky < 3; ky++) {
#pragma unroll 2
        for (int ci = 0; ci < NF; ci++) {
            const float* row = &s_in[(ky * NF + ci) * PADF];
            float4 wA = *(const float4*)&row[0];
            float4 wB = *(const float4*)&row[4];
            float4 wC = *(const float4*)&row[8];
            float4 wD = *(const float4*)&row[12];
            float2 wE = *(const float2*)&row[16];
            ull p0 = pack2(wA.x, wA.y), p1 = pack2(wA.z, wA.w);
            ull p2 = pack2(wB.x, wB.y), p3 = pack2(wB.z, wB.w);
            ull p4 = pack2(wC.x, wC.y), p5 = pack2(wC.z, wC.w);
            ull p6 = pack2(wD.x, wD.y), p7 = pack2(wD.z, wD.w);
            ull p8 = pack2(wE.x, wE.y);
            ull q0 = pack2(wA.y, wA.z), q1 = pack2(wA.w, wB.x);
            ull q2 = pack2(wB.y, wB.z), q3 = pack2(wB.w, wC.x);
            ull q4 = pack2(wC.y, wC.z), q5 = pack2(wC.w, wD.x);
            ull q6 = pack2(wD.y, wD.z), q7 = pack2(wD.w, wE.x);

            const float* wb = &wc[((ky * 3) * NF + ci) * CI + t];
            ull wv0 = dup2(wb[0]);
            ull wv1 = dup2(wb[NF * CI]);
            ull wv2 = dup2(wb[2 * NF * CI]);

            fma2(acc[0], p0, wv0); fma2(acc[1], p1, wv0);
            fma2(acc[2], p2, wv0); fma2(acc[3], p3, wv0);
            fma2(acc[4], p4, wv0); fma2(acc[5], p5, wv0);
            fma2(acc[6], p6, wv0); fma2(acc[7], p7, wv0);

            fma2(acc[0], q0, wv1); fma2(acc[1], q1, wv1);
            fma2(acc[2], q2, wv1); fma2(acc[3], q3, wv1);
            fma2(acc[4], q4, wv1); fma2(acc[5], q5, wv1);
            fma2(acc[6], q6, wv1); fma2(acc[7], q7, wv1);

            fma2(acc[0], p1, wv2); fma2(acc[1], p2, wv2);
            fma2(acc[2], p3, wv2); fma2(acc[3], p4, wv2);
            fma2(acc[4], p5, wv2); fma2(acc[5], p6, wv2);
            fma2(acc[6], p7, wv2); fma2(acc[7], p8, wv2);
        }
    }
#pragma unroll
    for (int p = 0; p < 8; p++) {
        float2 v = unpk(acc[p]);
        int gi0 = ((b * HH + y) * WW + x0 + 2 * p) * CI + t;
        out[gi0]      = x[gi0]      + v.x;
        out[gi0 + CI] = x[gi0 + CI] + v.y;
    }
}

// ---------------------------------------------------------------------------
extern "C" void kernel_launch(void* const* d_in, const int* in_sizes, int n_in,
                              void* d_out, int out_size)
{
    const float* x  = (const float*)d_in[0];
    const float* wt = (const float*)d_in[1];
    const float* wp = (const float*)d_in[2];
    const float* wg = (const float*)d_in[3];
    const float* wc = (const float*)d_in[4];
    float* out = (float*)d_out;

    const int smem_qkv   = 3 * CI * PADQ * 4;                 // 61440
    const int smem_flash = (128 * LDQ + 2 * 128 * LD) * 4;    // 186368
    const int smem_final = 3 * NF * PADF * 4;                 // 30720

    cudaFuncSetAttribute(conv_qkv_kernel,   cudaFuncAttributeMaxDynamicSharedMemorySize, smem_qkv);
    cudaFuncSetAttribute(flash_kernel,      cudaFuncAttributeMaxDynamicSharedMemorySize, smem_flash);
    cudaFuncSetAttribute(conv_final_kernel, cudaFuncAttributeMaxDynamicSharedMemorySize, smem_final);

    const int qtiles = (NPIX + QROWS - 1) / QROWS;            // 67

    conv_qkv_kernel<<<dim3(5, 80, 6), 256, smem_qkv>>>(x, wt, wp, wg);
    flash_kernel<<<dim3(qtiles, 2), 256, smem_flash>>>();
    conv_final_kernel<<<dim3(5, 80, 2), 256, smem_final>>>(x, wc, out);
}

// round 4
// speedup vs baseline: 1.4229x; 1.1422x over previous
#include <cuda_runtime.h>
#include <math.h>

#define HH 80
#define WW 80
#define CI 256
#define NF 128
#define NPIX (HH*WW)   // 6400
#define BATCH 2

// Scratch (device globals; no allocations allowed)
__device__ float g_qkv[3][BATCH][NPIX*NF];   // theta, phi(flat), g
__device__ float g_att[BATCH][NPIX*NF];      // attention output (n, c)

// ---------------- packed f32x2 helpers (FFMA2 via PTX) ----------------------
typedef unsigned long long ull;

__device__ __forceinline__ ull pack2(float lo, float hi) {
    ull r; asm("mov.b64 %0, {%1, %2};" : "=l"(r) : "f"(lo), "f"(hi)); return r;
}
__device__ __forceinline__ ull dup2(float v) { return pack2(v, v); }
__device__ __forceinline__ void fma2(ull& d, ull a, ull b) {
    asm("fma.rn.f32x2 %0, %1, %2, %3;" : "=l"(d) : "l"(a), "l"(b), "l"(d));
}
__device__ __forceinline__ float2 unpk(ull v) {
    float2 f; asm("mov.b64 {%0, %1}, %2;" : "=f"(f.x), "=f"(f.y) : "l"(v)); return f;
}

// ---------------------------------------------------------------------------
// Conv 3x3 SAME, CIN=256 -> CO=128, computes theta/phi/g (blockIdx.z % 3)
// Tile: 2 rows x 16 px x 128 co. Block 128 threads.
// Thread: co-pair c2 = 2*(t%64), row r = t/64; computes 16 px x 2 co.
// Weights packed over co (aligned LDG.64), pixel dup2 reused over kx and co.
// ---------------------------------------------------------------------------
#define PADQ 20
__global__ __launch_bounds__(128) void conv_qkv_kernel(
    const float* __restrict__ x,
    const float* __restrict__ w0,
    const float* __restrict__ w1,
    const float* __restrict__ w2)
{
    extern __shared__ float s_in[];            // [4][CI][PADQ] (18 used)
    const int x0 = blockIdx.x * 16;
    const int y0 = blockIdx.y * 2;
    const int b  = blockIdx.z / 3;
    const int cv = blockIdx.z % 3;
    const float* __restrict__ wgt = (cv == 0) ? w0 : ((cv == 1) ? w1 : w2);
    float* __restrict__ outp = g_qkv[cv][b];
    const int t = threadIdx.x;

    // Patch: rows y0-1 .. y0+2, x0-1 .. x0+16, all 256 ci
    for (int i = t; i < 4 * 18 * CI; i += 128) {
        int ci = i & (CI - 1);
        int xi = (i >> 8) % 18;
        int r  = i / (18 * CI);
        int gy = y0 - 1 + r, gx = x0 - 1 + xi;
        float v = 0.f;
        if (gy >= 0 && gy < HH && gx >= 0 && gx < WW)
            v = x[((b * HH + gy) * WW + gx) * CI + ci];
        s_in[(r * CI + ci) * PADQ + xi] = v;
    }
    __syncthreads();

    const int c2 = (t & 63) * 2;
    const int r  = t >> 6;

    ull acc[16];
#pragma unroll
    for (int p = 0; p < 16; p++) acc[p] = dup2(0.f);

    const int kstride = CI * NF;   // weight offset per kx

    for (int ky = 0; ky < 3; ky++) {
        const float* srow0 = &s_in[((r + ky) * CI) * PADQ];
        const float* wbase = &wgt[(ky * 3 * CI) * NF + c2];
        // prefetch ci=0 weights
        ull nw0 = *(const ull*)&wbase[0];
        ull nw1 = *(const ull*)&wbase[kstride];
        ull nw2 = *(const ull*)&wbase[2 * kstride];
#pragma unroll 1
        for (int ci = 0; ci < CI; ci++) {
            ull wv0 = nw0, wv1 = nw1, wv2 = nw2;
            if (ci + 1 < CI) {
                const float* wn = wbase + (ci + 1) * NF;
                nw0 = *(const ull*)&wn[0];
                nw1 = *(const ull*)&wn[kstride];
                nw2 = *(const ull*)&wn[2 * kstride];
            }
            const float* row = srow0 + ci * PADQ;
            float4 wA = *(const float4*)&row[0];
            float4 wB = *(const float4*)&row[4];
            float4 wC = *(const float4*)&row[8];
            float4 wD = *(const float4*)&row[12];
            float2 wE = *(const float2*)&row[16];
            ull wd[18];
            wd[0]=dup2(wA.x); wd[1]=dup2(wA.y); wd[2]=dup2(wA.z); wd[3]=dup2(wA.w);
            wd[4]=dup2(wB.x); wd[5]=dup2(wB.y); wd[6]=dup2(wB.z); wd[7]=dup2(wB.w);
            wd[8]=dup2(wC.x); wd[9]=dup2(wC.y); wd[10]=dup2(wC.z); wd[11]=dup2(wC.w);
            wd[12]=dup2(wD.x); wd[13]=dup2(wD.y); wd[14]=dup2(wD.z); wd[15]=dup2(wD.w);
            wd[16]=dup2(wE.x); wd[17]=dup2(wE.y);
#pragma unroll
            for (int p = 0; p < 16; p++) {
                fma2(acc[p], wd[p],     wv0);
                fma2(acc[p], wd[p + 1], wv1);
                fma2(acc[p], wd[p + 2], wv2);
            }
        }
    }
    const int nbase = (y0 + r) * WW + x0;
#pragma unroll
    for (int p = 0; p < 16; p++) {
        float2 v = unpk(acc[p]);
        *(float2*)&outp[(nbase + p) * NF + c2] = v;
    }
}

// ---------------------------------------------------------------------------
// Flash attention: out = softmax(theta @ phiview) @ g,  N=6400, d=128.
// phiview(c, m) = phi_flat[c*6400 + m]. Q-tile = 96 rows -> 67x2=134 CTAs.
// Block 256 threads, frag 6x8, packed f32x2. float4 chunk staging.
// ---------------------------------------------------------------------------
#define LD  132
#define LDQ 100
#define QROWS 96
#define SM_Q 0
#define SM_B (128*LDQ)
#define SM_G (128*LDQ + 128*LD)

__global__ __launch_bounds__(256, 1) void flash_kernel()
{
    extern __shared__ float sm[];
    float* Qst = sm + SM_Q;   // [c][i] transposed, i < 96
    float* Bs  = sm + SM_B;   // K-chunk, then reused as P
    float* Gs  = sm + SM_G;

    const int b  = blockIdx.y;
    const int q0 = blockIdx.x * QROWS;
    const float* __restrict__ theta = g_qkv[0][b];
    const float* __restrict__ phi   = g_qkv[1][b];
    const float* __restrict__ gmat  = g_qkv[2][b];

    const int t  = threadIdx.x;
    const int tx = t & 15, ty = t >> 4;
    const int i0 = ty * 6, j0 = tx * 8;

    // Load Q tile transposed: Qst[c*LDQ + i]  (rows clamped at edge tile)
    for (int idx = t; idx < QROWS * 128; idx += 256) {
        int i = idx >> 7, c = idx & 127;
        int qi = q0 + i; if (qi >= NPIX) qi = NPIX - 1;
        Qst[c * LDQ + i] = theta[qi * NF + c];
    }

    ull o2[6][4];
    float mrun[6], lrun[6];
#pragma unroll
    for (int ii = 0; ii < 6; ii++) {
        mrun[ii] = -1e30f; lrun[ii] = 0.f;
#pragma unroll
        for (int cp = 0; cp < 4; cp++) o2[ii][cp] = dup2(0.f);
    }
    __syncthreads();

    for (int km = 0; km < 50; km++) {
        const int m0 = km * 128;
        // float4 staging of K-chunk and G-chunk
#pragma unroll
        for (int idx = t; idx < 4096; idx += 256) {
            int rr = idx >> 5;
            int cc = (idx & 31) << 2;
            *(float4*)&Bs[rr * LD + cc] = *(const float4*)&phi[rr * NPIX + m0 + cc];
            *(float4*)&Gs[rr * LD + cc] = *(const float4*)&gmat[(m0 + rr) * NF + cc];
        }
        __syncthreads();

        // GEMM1: S = Q @ B  (96x128x128), packed along j
        ull s2[6][4];
#pragma unroll
        for (int ii = 0; ii < 6; ii++)
#pragma unroll
            for (int jp = 0; jp < 4; jp++) s2[ii][jp] = dup2(0.f);

        for (int c = 0; c < 128; c++) {
            const float* qrow = &Qst[c * LDQ + i0];
            float2 a01 = *(const float2*)&qrow[0];
            float2 a23 = *(const float2*)&qrow[2];
            float2 a45 = *(const float2*)&qrow[4];
            ull av[6] = {dup2(a01.x), dup2(a01.y), dup2(a23.x),
                         dup2(a23.y), dup2(a45.x), dup2(a45.y)};
            const ulonglong2* brow = (const ulonglong2*)&Bs[c * LD + j0];
            ulonglong2 b01 = brow[0], b23 = brow[1];
            ull bv[4] = {b01.x, b01.y, b23.x, b23.y};
#pragma unroll
            for (int ii = 0; ii < 6; ii++)
#pragma unroll
                for (int jp = 0; jp < 4; jp++)
                    fma2(s2[ii][jp], av[ii], bv[jp]);
        }
        __syncthreads();   // done reading Bs; safe to overwrite with P

        // Online softmax update (row stats reduced across the 16 tx lanes)
#pragma unroll
        for (int ii = 0; ii < 6; ii++) {
            float sv[8];
            float2 u;
            u = unpk(s2[ii][0]); sv[0] = u.x; sv[1] = u.y;
            u = unpk(s2[ii][1]); sv[2] = u.x; sv[3] = u.y;
            u = unpk(s2[ii][2]); sv[4] = u.x; sv[5] = u.y;
            u = unpk(s2[ii][3]); sv[6] = u.x; sv[7] = u.y;
            float mx = sv[0];
#pragma unroll
            for (int jj = 1; jj < 8; jj++) mx = fmaxf(mx, sv[jj]);
            mx = fmaxf(mx, __shfl_xor_sync(0xffffffffu, mx, 1));
            mx = fmaxf(mx, __shfl_xor_sync(0xffffffffu, mx, 2));
            mx = fmaxf(mx, __shfl_xor_sync(0xffffffffu, mx, 4));
            mx = fmaxf(mx, __shfl_xor_sync(0xffffffffu, mx, 8));
            float mnew = fmaxf(mrun[ii], mx);
            float f = __expf(mrun[ii] - mnew);
            mrun[ii] = mnew;
            float sum = 0.f;
#pragma unroll
            for (int jj = 0; jj < 8; jj++) {
                float p = __expf(sv[jj] - mnew);
                sv[jj] = p;
                sum += p;
            }
            sum += __shfl_xor_sync(0xffffffffu, sum, 1);
            sum += __shfl_xor_sync(0xffffffffu, sum, 2);
            sum += __shfl_xor_sync(0xffffffffu, sum, 4);
            sum += __shfl_xor_sync(0xffffffffu, sum, 8);
            lrun[ii] = lrun[ii] * f + sum;
            ull f2v = dup2(f);
#pragma unroll
            for (int cp = 0; cp < 4; cp++) {
                ull z = dup2(0.f);
                fma2(z, o2[ii][cp], f2v);   // o *= f
                o2[ii][cp] = z;
            }
            // stash P row into Bs (P[i][j] layout)
            *(float4*)&Bs[(i0 + ii) * LD + j0]     = make_float4(sv[0], sv[1], sv[2], sv[3]);
            *(float4*)&Bs[(i0 + ii) * LD + j0 + 4] = make_float4(sv[4], sv[5], sv[6], sv[7]);
        }
        __syncthreads();

        // GEMM2: O += P @ G  (channels j0..j0+7, packed)
        for (int j = 0; j < 128; j++) {
            const ulonglong2* grow = (const ulonglong2*)&Gs[j * LD + j0];
            ulonglong2 g01 = grow[0], g23 = grow[1];
            ull gv[4] = {g01.x, g01.y, g23.x, g23.y};
#pragma unroll
            for (int ii = 0; ii < 6; ii++) {
                ull pv = dup2(Bs[(i0 + ii) * LD + j]);   // broadcast LDS
#pragma unroll
                for (int cp = 0; cp < 4; cp++)
                    fma2(o2[ii][cp], pv, gv[cp]);
            }
        }
        __syncthreads();   // GEMM2 reads done before next chunk's loads
    }

    // Epilogue: normalize and store (n, c) layout
#pragma unroll
    for (int ii = 0; ii < 6; ii++) {
        int row = q0 + i0 + ii;
        if (row >= NPIX) continue;
        float inv = 1.f / lrun[ii];
        float2 v0 = unpk(o2[ii][0]), v1 = unpk(o2[ii][1]);
        float2 v2 = unpk(o2[ii][2]), v3 = unpk(o2[ii][3]);
        float* dst = &g_att[b][row * NF + j0];
        *(float4*)&dst[0] = make_float4(v0.x * inv, v0.y * inv, v1.x * inv, v1.y * inv);
        *(float4*)&dst[4] = make_float4(v2.x * inv, v2.y * inv, v3.x * inv, v3.y * inv);
    }
}

// ---------------------------------------------------------------------------
// Final conv 3x3, 128 -> 256, + residual add, writes d_out.
// Tile: 2 rows x 16 px x 256 co. Block 256 threads.
// Thread: co-pair c2 = 2*(t%128), row r = t/128; 16 px x 2 co.
// ---------------------------------------------------------------------------
#define PADF 20
__global__ __launch_bounds__(256) void conv_final_kernel(
    const float* __restrict__ x,
    const float* __restrict__ wc,
    float* __restrict__ out)
{
    extern __shared__ float s_in[];            // [4][NF][PADF]
    const int x0 = blockIdx.x * 16;
    const int y0 = blockIdx.y * 2;
    const int b  = blockIdx.z;
    const int t  = threadIdx.x;
    const float* __restrict__ ain = g_att[b];

    for (int i = t; i < 4 * 18 * NF; i += 256) {
        int ci = i & (NF - 1);
        int xi = (i >> 7) % 18;
        int r  = i / (18 * NF);
        int gy = y0 - 1 + r, gx = x0 - 1 + xi;
        float v = 0.f;
        if (gy >= 0 && gy < HH && gx >= 0 && gx < WW)
            v = ain[(gy * WW + gx) * NF + ci];
        s_in[(r * NF + ci) * PADF + xi] = v;
    }
    __syncthreads();

    const int c2 = (t & 127) * 2;
    const int r  = t >> 7;

    ull acc[16];
#pragma unroll
    for (int p = 0; p < 16; p++) acc[p] = dup2(0.f);

    const int kstride = NF * CI;

    for (int ky = 0; ky < 3; ky++) {
        const float* srow0 = &s_in[((r + ky) * NF) * PADF];
        const float* wbase = &wc[(ky * 3 * NF) * CI + c2];
        ull nw0 = *(const ull*)&wbase[0];
        ull nw1 = *(const ull*)&wbase[kstride];
        ull nw2 = *(const ull*)&wbase[2 * kstride];
#pragma unroll 1
        for (int ci = 0; ci < NF; ci++) {
            ull wv0 = nw0, wv1 = nw1, wv2 = nw2;
            if (ci + 1 < NF) {
                const float* wn = wbase + (ci + 1) * CI;
                nw0 = *(const ull*)&wn[0];
                nw1 = *(const ull*)&wn[kstride];
                nw2 = *(const ull*)&wn[2 * kstride];
            }
            const float* row = srow0 + ci * PADF;
            float4 wA = *(const float4*)&row[0];
            float4 wB = *(const float4*)&row[4];
            float4 wC = *(const float4*)&row[8];
            float4 wD = *(const float4*)&row[12];
            float2 wE = *(const float2*)&row[16];
            ull wd[18];
            wd[0]=dup2(wA.x); wd[1]=dup2(wA.y); wd[2]=dup2(wA.z); wd[3]=dup2(wA.w);
            wd[4]=dup2(wB.x); wd[5]=dup2(wB.y); wd[6]=dup2(wB.z); wd[7]=dup2(wB.w);
            wd[8]=dup2(wC.x); wd[9]=dup2(wC.y); wd[10]=dup2(wC.z); wd[11]=dup2(wC.w);
            wd[12]=dup2(wD.x); wd[13]=dup2(wD.y); wd[14]=dup2(wD.z); wd[15]=dup2(wD.w);
            wd[16]=dup2(wE.x); wd[17]=dup2(wE.y);
#pragma unroll
            for (int p = 0; p < 16; p++) {
                fma2(acc[p], wd[p],     wv0);
                fma2(acc[p], wd[p + 1], wv1);
                fma2(acc[p], wd[p + 2], wv2);
            }
        }
    }
#pragma unroll
    for (int p = 0; p < 16; p++) {
        float2 v = unpk(acc[p]);
        int gi = ((b * HH + y0 + r) * WW + x0 + p) * CI + c2;
        float2 xv = *(const float2*)&x[gi];
        *(float2*)&out[gi] = make_float2(xv.x + v.x, xv.y + v.y);
    }
}

// ---------------------------------------------------------------------------
extern "C" void kernel_launch(void* const* d_in, const int* in_sizes, int n_in,
                              void* d_out, int out_size)
{
    const float* x  = (const float*)d_in[0];
    const float* wt = (const float*)d_in[1];
    const float* wp = (const float*)d_in[2];
    const float* wg = (const float*)d_in[3];
    const float* wc = (const float*)d_in[4];
    float* out = (float*)d_out;

    const int smem_qkv   = 4 * CI * PADQ * 4;                 // 81920
    const int smem_flash = (128 * LDQ + 2 * 128 * LD) * 4;    // 186368
    const int smem_final = 4 * NF * PADF * 4;                 // 40960

    cudaFuncSetAttribute(conv_qkv_kernel,   cudaFuncAttributeMaxDynamicSharedMemorySize, smem_qkv);
    cudaFuncSetAttribute(flash_kernel,      cudaFuncAttributeMaxDynamicSharedMemorySize, smem_flash);
    cudaFuncSetAttribute(conv_final_kernel, cudaFuncAttributeMaxDynamicSharedMemorySize, smem_final);

    const int qtiles = (NPIX + QROWS - 1) / QROWS;            // 67

    conv_qkv_kernel<<<dim3(5, 40, 6), 128, smem_qkv>>>(x, wt, wp, wg);
    flash_kernel<<<dim3(qtiles, 2), 256, smem_flash>>>();
    conv_final_kernel<<<dim3(5, 40, 2), 256, smem_final>>>(x, wc, out);
}